// round 17
// baseline (speedup 1.0000x reference)
#include <cuda_runtime.h>
#include <cstdint>

// EmbeddingLayer: 16 sparse gathers + 2 sequence poolings (sum, nonzero-mean) + dense concat.
//
// R17 = R14 (uniform blocks, evict_last pinning, streaming output) with the
//       pooling gathers widened to 256-bit loads:
//   ld.global.nc.L2::evict_last.v8.b32 -- lane (rg,e) loads 32B of row rg in a
//   4-row group; one warp instruction covers 4 rows (2x fewer LDG instructions
//   and L1 requests than the 16-lane float4 scheme). Cross-row-group reduce via
//   shfl_xor(8)+shfl_xor(16); lanes 0..7 write 8 floats each.

#define VOCAB   100000
#define BATCH   4096
#define EMBED   64
#define SEQLEN  50
#define NSPARSE 16
#define NDENSE  13
#define ROW_OUT (NSPARSE * EMBED + 2 * EMBED + NDENSE)  // 1165

#define ROWS_PER_BLOCK 4
#define GRID_BLOCKS (BATCH / ROWS_PER_BLOCK)   // 1024
#define THREADS 256

__device__ __forceinline__ uint64_t evict_last_policy() {
    uint64_t p;
    asm("createpolicy.fractional.L2::evict_last.b64 %0, 1.0;" : "=l"(p));
    return p;
}
__device__ __forceinline__ float4 ldg_el(const float4* p, uint64_t pol) {
    float4 v;
    asm volatile("ld.global.nc.L2::cache_hint.v4.f32 {%0,%1,%2,%3}, [%4], %5;"
                 : "=f"(v.x), "=f"(v.y), "=f"(v.z), "=f"(v.w)
                 : "l"(p), "l"(pol));
    return v;
}
__device__ __forceinline__ int ldg_el_i(const int* p, uint64_t pol) {
    int v;
    asm volatile("ld.global.nc.L2::cache_hint.s32 %0, [%1], %2;"
                 : "=r"(v) : "l"(p), "l"(pol));
    return v;
}
// 256-bit gather with inline evict_last (legal on v8.b32)
__device__ __forceinline__ void ldg256_el(const float* p, uint32_t* v) {
    asm volatile("ld.global.nc.L2::evict_last.v8.b32 "
                 "{%0,%1,%2,%3,%4,%5,%6,%7}, [%8];"
                 : "=r"(v[0]), "=r"(v[1]), "=r"(v[2]), "=r"(v[3]),
                   "=r"(v[4]), "=r"(v[5]), "=r"(v[6]), "=r"(v[7])
                 : "l"(p));
}

__global__ __launch_bounds__(THREADS, 4)
void embedding_layer_kernel(const float4* __restrict__ sp_tab,   // [16*VOCAB*16] float4
                            const float4* __restrict__ seq_tab,  // [ 2*VOCAB*16] float4
                            const float*  __restrict__ dense,    // [BATCH*13]
                            const int*    __restrict__ sp_idx,   // [16*BATCH]
                            const int*    __restrict__ sq_idx,   // [2*BATCH*50]
                            float*        __restrict__ out)      // [BATCH*1165]
{
    const int tid = threadIdx.x;
    const uint64_t pol = evict_last_policy();
    const int b0 = blockIdx.x * ROWS_PER_BLOCK;

    // ---- sparse copy: iteration k handles batch row b0+k completely ----
    {
        const int f = tid >> 4;      // feature 0..15
        const int q = tid & 15;      // float4 lane 0..15
        #pragma unroll
        for (int k = 0; k < ROWS_PER_BLOCK; k++) {
            const int b = b0 + k;
            int idx = __ldg(&sp_idx[f * BATCH + b]);
            float4 v = ldg_el(&sp_tab[((size_t)f * VOCAB + idx) * 16 + q], pol);
            float* o = out + (size_t)b * ROW_OUT + f * EMBED + q * 4;
            __stcs(&o[0], v.x); __stcs(&o[1], v.y);
            __stcs(&o[2], v.z); __stcs(&o[3], v.w);
        }
    }

    // ---- dense tail: 4 rows x 13 floats = 52 items ----
    if (tid < ROWS_PER_BLOCK * NDENSE) {
        const int b = b0 + tid / NDENSE;
        const int j = tid % NDENSE;
        __stcs(&out[(size_t)b * ROW_OUT + (NSPARSE + 2) * EMBED + j],
               __ldg(&dense[(size_t)b * NDENSE + j]));
    }

    // ---- seq pooling: one warp per (batch row, feature), 4 rows per LDG.256 ----
    {
        const int warp = tid >> 5;                       // 0..7
        const int lane = tid & 31;
        const int pb   = b0 + (warp >> 1);
        const int feat = warp & 1;                       // 0: sum, 1: nonzero-mean
        const int e    = lane & 7;                       // eighth: embed floats e*8..e*8+7
        const int rg   = lane >> 3;                      // row-in-group 0..3

        const int* __restrict__ ip =
            sq_idx + ((size_t)feat * BATCH + pb) * SEQLEN;
        const float* __restrict__ tab =
            (const float*)(seq_tab + (size_t)feat * VOCAB * 16);

        // cooperative index load: lane l holds ip[l]; lanes 0..17 also ip[32+l]
        int idx_a = ldg_el_i(&ip[lane], pol);
        int idx_b = (lane < SEQLEN - 32) ? ldg_el_i(&ip[32 + lane], pol) : 0;

        float acc[8], cnt[8];
        #pragma unroll
        for (int j = 0; j < 8; j++) { acc[j] = 0.f; cnt[j] = 0.f; }

        // 12 full iterations: rows it*4+rg (0..47)
        #pragma unroll
        for (int it = 0; it < 12; it++) {
            int idx = (it < 8)
                ? __shfl_sync(0xFFFFFFFFu, idx_a, it * 4 + rg)
                : __shfl_sync(0xFFFFFFFFu, idx_b, (it - 8) * 4 + rg);
            uint32_t v[8];
            ldg256_el(tab + (size_t)idx * EMBED + e * 8, v);
            #pragma unroll
            for (int j = 0; j < 8; j++) {
                float f = __uint_as_float(v[j]);
                acc[j] += f;
                if (feat) cnt[j] += (f != 0.f) ? 1.f : 0.f;
            }
        }
        // tail: rows 48,49 handled by row-groups 0,1
        {
            int idx = __shfl_sync(0xFFFFFFFFu, idx_b, 16 + (rg & 1));
            if (rg < 2) {
                uint32_t v[8];
                ldg256_el(tab + (size_t)idx * EMBED + e * 8, v);
                #pragma unroll
                for (int j = 0; j < 8; j++) {
                    float f = __uint_as_float(v[j]);
                    acc[j] += f;
                    if (feat) cnt[j] += (f != 0.f) ? 1.f : 0.f;
                }
            }
        }

        // reduce across the 4 row-groups (lanes e, e+8, e+16, e+24 share dims)
        #pragma unroll
        for (int j = 0; j < 8; j++) {
            acc[j] += __shfl_xor_sync(0xFFFFFFFFu, acc[j], 8);
            acc[j] += __shfl_xor_sync(0xFFFFFFFFu, acc[j], 16);
        }
        if (feat) {
            #pragma unroll
            for (int j = 0; j < 8; j++) {
                cnt[j] += __shfl_xor_sync(0xFFFFFFFFu, cnt[j], 8);
                cnt[j] += __shfl_xor_sync(0xFFFFFFFFu, cnt[j], 16);
            }
        }

        if (rg == 0) {   // lanes 0..7 write 8 floats each
            float* o = out + (size_t)pb * ROW_OUT + (NSPARSE + feat) * EMBED + e * 8;
            if (feat == 0) {
                #pragma unroll
                for (int j = 0; j < 8; j++) __stcs(&o[j], acc[j]);
            } else {
                #pragma unroll
                for (int j = 0; j < 8; j++)
                    __stcs(&o[j], acc[j] / (cnt[j] + 1e-16f));
            }
        }
    }
}

extern "C" void kernel_launch(void* const* d_in, const int* in_sizes, int n_in,
                              void* d_out, int out_size) {
    const float* sp_tab  = (const float*)d_in[0];
    const float* seq_tab = (const float*)d_in[1];
    const float* dense   = (const float*)d_in[2];
    const int*   sp_idx  = (const int*)d_in[3];
    const int*   sq_idx  = (const int*)d_in[4];
    float*       out     = (float*)d_out;

    embedding_layer_kernel<<<GRID_BLOCKS, THREADS>>>(
        (const float4*)sp_tab, (const float4*)seq_tab, dense, sp_idx, sq_idx, out);
}